// round 16
// baseline (speedup 1.0000x reference)
#include <cuda_runtime.h>

#define SEQ   2048
#define H     128
#define B     64
#define OUTF  512
#define NREC  64
#define NFC   84
#define THREADS 256

// Scratch: hidden-state history + per-batch progress watermark
__device__ float g_hs[(size_t)B * SEQ * H];
__device__ int   g_wm[B];

__device__ __forceinline__ unsigned long long ffma2(unsigned long long a,
                                                    unsigned long long b,
                                                    unsigned long long c) {
    unsigned long long d;
    asm("fma.rn.f32x2 %0, %1, %2, %3;" : "=l"(d) : "l"(a), "l"(b), "l"(c));
    return d;
}
__device__ __forceinline__ unsigned long long add2(unsigned long long a,
                                                   unsigned long long b) {
    unsigned long long d;
    asm("add.rn.f32x2 %0, %1, %2;" : "=l"(d) : "l"(a), "l"(b));
    return d;
}
__device__ __forceinline__ float hsum2(unsigned long long v) {
    float lo, hi;
    asm("mov.b64 {%0, %1}, %2;" : "=f"(lo), "=f"(hi) : "l"(v));
    return lo + hi;
}
__device__ __forceinline__ float ex2f(float x) {
    float y; asm("ex2.approx.f32 %0, %1;" : "=f"(y) : "f"(x)); return y;
}
__device__ __forceinline__ float rcpf(float x) {
    float y; asm("rcp.approx.f32 %0, %1;" : "=f"(y) : "f"(x)); return y;
}
__device__ __forceinline__ float fast_sigmoid(float x) {
    return rcpf(1.0f + ex2f(-1.4426950408889634f * x));
}
__device__ __forceinline__ float tanh_fast(float x) {
    float y; asm("tanh.approx.f32 %0, %1;" : "=f"(y) : "f"(x)); return y;
}

__global__ void init_wm_kernel() {
    if (threadIdx.x < B) g_wm[threadIdx.x] = 0;
}

// Recurrence smem layout: parity p at pool + p*264:
//   copy A (read by half 0) at +0,  copy B (read by half 1) at +132
// 132-float shift => the two broadcast lines land in different banks.
#define PAR_STRIDE 264

__global__ void __launch_bounds__(THREADS, 1) fused_kernel(
    const float* __restrict__ latent,  // (64,128)
    const float* __restrict__ W_hh,    // (384,128)
    const float* __restrict__ b_ih,    // (384,)
    const float* __restrict__ b_hh,    // (384,)
    const float* __restrict__ fc_W,    // (512,128)
    const float* __restrict__ fc_b,    // (512,)
    float* __restrict__ out)           // (64,2048,512)
{
    __shared__ __align__(16) float pool[32 * H];

    const int tid = threadIdx.x;

    if (blockIdx.x < NREC) {
        // === Recurrence: one batch/CTA; a lane PAIR owns hidden index li and ===
        // === computes r, z, n dots itself. Ping-pong h, ONE barrier per step. ===
        const int b    = blockIdx.x;
        const int lane = tid & 31;
        const int warp = tid >> 5;            // 0..7
        const int half = lane & 1;            // low/high 64 elems of each dot
        const int li   = warp * 16 + (lane >> 1);   // 0..127

        // Three half-rows of W_hh in registers: 96 u64 = 192 regs
        unsigned long long wr[32], wz[32], wn[32];
        {
            const unsigned long long* W64 = (const unsigned long long*)W_hh;
            const size_t o  = (size_t)half * 32;
            const size_t rr = (size_t)li * 64;
            const size_t rz = (size_t)(H + li) * 64;
            const size_t rn = (size_t)(2 * H + li) * 64;
            #pragma unroll
            for (int k = 0; k < 32; k++) wr[k] = W64[rr + o + k];
            #pragma unroll
            for (int k = 0; k < 32; k++) wz[k] = W64[rz + o + k];
            #pragma unroll
            for (int k = 0; k < 32; k++) wn[k] = W64[rn + o + k];
        }

        const float bs_r   = b_ih[li] + b_hh[li];
        const float bs_z   = b_ih[H + li] + b_hh[H + li];
        const float bs_n   = b_hh[2 * H + li];
        const float b_in_i = b_ih[2 * H + li];

        // h[li] lives in a register across steps (owned by this lane pair)
        float hold = latent[(size_t)b * H + li];
        pool[half * 132 + li] = hold;          // init parity-0 buffers
        __syncthreads();

        const int widx = half * 132 + li;      // write index within a parity region
        const int roff = half ? 196 : 0;       // read offset within a parity region

        const float* rb0 = pool + roff;              // parity 0 read base
        const float* rb1 = pool + PAR_STRIDE + roff; // parity 1 read base
        float*       wb0 = pool;                     // parity 0 write base
        float*       wb1 = pool + PAR_STRIDE;

        float* hs_base = g_hs + (size_t)b * SEQ * H + li;

        // one GRU step: read h from rbase, write new h to wbase
        auto step = [&](const float* rbase, float* wbase, int t) {
            const ulonglong2* h2 = (const ulonglong2*)rbase;
            unsigned long long ar = 0ull, az = 0ull, an = 0ull;
            #pragma unroll
            for (int k = 0; k < 16; k++) {
                ulonglong2 hv = h2[k];
                ar = ffma2(wr[2 * k], hv.x, ar);
                az = ffma2(wz[2 * k], hv.x, az);
                an = ffma2(wn[2 * k], hv.x, an);
                ar = ffma2(wr[2 * k + 1], hv.y, ar);
                az = ffma2(wz[2 * k + 1], hv.y, az);
                an = ffma2(wn[2 * k + 1], hv.y, an);
            }
            // Critical path: sr -> r -> n -> hn. Reduce sr first.
            float sr = hsum2(ar);
            float sn = hsum2(an);
            float sz = hsum2(az);
            sr += __shfl_xor_sync(0xffffffffu, sr, 1);
            sn += __shfl_xor_sync(0xffffffffu, sn, 1);
            sz += __shfl_xor_sync(0xffffffffu, sz, 1);

            float r   = fast_sigmoid(sr + bs_r);
            float snb = sn + bs_n;                    // off critical path
            float z   = fast_sigmoid(sz + bs_z);      // parallel chain
            float zh  = z * hold;                     // ready before n
            float omz = 1.0f - z;                     // ready before n
            float n   = tanh_fast(fmaf(r, snb, b_in_i));  // single MUFU
            float hn  = fmaf(omz, n, zh);             // ONE fma after tanh
            hold = hn;

            wbase[widx] = hn;                    // ping-pong write (no WAR race)
            if (half == 0) hs_base[(size_t)t * H] = hn;
            __syncthreads();                     // single barrier per step
        };

        for (int to = 0; to < SEQ; to += 64) {   // watermark cadence: 64 steps
            #pragma unroll 1
            for (int ti = 0; ti < 64; ti += 2) {
                step(rb0, wb1, to + ti);         // even step: parity 0 -> 1
                step(rb1, wb0, to + ti + 1);     // odd  step: parity 1 -> 0
            }
            if (tid == 0) {
                __threadfence();
                atomicExch(&g_wm[b], to + 64);
            }
        }
    } else {
        // ================= FC role: consume hs tiles as produced =================
        const int fcid = blockIdx.x - NREC;   // 0..83
        const int cb   = fcid / 21;           // fixed 128-col block
        const int sub  = fcid % 21;
        const int col  = cb * H + (tid & 127);
        const int grp  = tid >> 7;            // 2 row-groups over the 32-row tile

        unsigned long long w[64];
        {
            const unsigned long long* Wr =
                (const unsigned long long*)(fc_W + (size_t)col * H);
            #pragma unroll
            for (int k = 0; k < 64; k++) w[k] = Wr[k];
        }
        const float bias = fc_b[col];

        for (int ent = sub; ent < 64 * B; ent += 21) {
            const int tblk = ent >> 6;
            const int bb   = ent & 63;

            if (tid == 0) {
                const int need = (tblk + 1) * 32;
                while (atomicAdd(&g_wm[bb], 0) < need) __nanosleep(256);
            }
            __syncthreads();

            // Stage 32x128 fp32 hs tile (16 KB)
            const float4* src =
                (const float4*)(g_hs + ((size_t)bb * SEQ + (size_t)tblk * 32) * H);
            float4* dst = (float4*)pool;
            #pragma unroll
            for (int it = 0; it < 4; it++) {
                int idx = tid + it * THREADS;
                dst[idx] = src[idx];
            }
            __syncthreads();

            for (int r = grp; r < 32; r += 2) {
                const ulonglong2* hrow = (const ulonglong2*)(pool + r * H);
                unsigned long long a0 = 0ull, a1 = 0ull;
                #pragma unroll
                for (int k = 0; k < 32; k++) {
                    ulonglong2 hv = hrow[k];
                    a0 = ffma2(w[2 * k    ], hv.x, a0);
                    a1 = ffma2(w[2 * k + 1], hv.y, a1);
                }
                out[((size_t)bb * SEQ + (size_t)tblk * 32 + r) * OUTF + col] =
                    hsum2(add2(a0, a1)) + bias;
            }
            __syncthreads();
        }
    }
}

extern "C" void kernel_launch(void* const* d_in, const int* in_sizes, int n_in,
                              void* d_out, int out_size) {
    const float* latent = (const float*)d_in[0];
    const float* W_hh   = (const float*)d_in[1];
    const float* b_ih   = (const float*)d_in[2];
    const float* b_hh   = (const float*)d_in[3];
    const float* fc_W   = (const float*)d_in[4];
    const float* fc_b   = (const float*)d_in[5];
    float* out = (float*)d_out;

    init_wm_kernel<<<1, 64>>>();
    fused_kernel<<<NREC + NFC, THREADS>>>(latent, W_hh, b_ih, b_hh, fc_W, fc_b, out);
}

// round 17
// speedup vs baseline: 1.0224x; 1.0224x over previous
#include <cuda_runtime.h>

#define SEQ   2048
#define H     128
#define B     64
#define OUTF  512
#define NREC  64
#define NFC   84
#define THREADS 256

// Scratch: hidden-state history + per-batch progress watermark
__device__ float g_hs[(size_t)B * SEQ * H];
__device__ int   g_wm[B];

__device__ __forceinline__ unsigned long long ffma2(unsigned long long a,
                                                    unsigned long long b,
                                                    unsigned long long c) {
    unsigned long long d;
    asm("fma.rn.f32x2 %0, %1, %2, %3;" : "=l"(d) : "l"(a), "l"(b), "l"(c));
    return d;
}
__device__ __forceinline__ unsigned long long add2(unsigned long long a,
                                                   unsigned long long b) {
    unsigned long long d;
    asm("add.rn.f32x2 %0, %1, %2;" : "=l"(d) : "l"(a), "l"(b));
    return d;
}
__device__ __forceinline__ float hsum2(unsigned long long v) {
    float lo, hi;
    asm("mov.b64 {%0, %1}, %2;" : "=f"(lo), "=f"(hi) : "l"(v));
    return lo + hi;
}
__device__ __forceinline__ float ex2f(float x) {
    float y; asm("ex2.approx.f32 %0, %1;" : "=f"(y) : "f"(x)); return y;
}
__device__ __forceinline__ float rcpf(float x) {
    float y; asm("rcp.approx.f32 %0, %1;" : "=f"(y) : "f"(x)); return y;
}
__device__ __forceinline__ float fast_sigmoid(float x) {
    return rcpf(1.0f + ex2f(-1.4426950408889634f * x));
}
__device__ __forceinline__ float tanh_fast(float x) {
    float y; asm("tanh.approx.f32 %0, %1;" : "=f"(y) : "f"(x)); return y;
}

__global__ void init_wm_kernel() {
    if (threadIdx.x < B) g_wm[threadIdx.x] = 0;
}

// Recurrence smem layout: parity p at pool + p*264:
//   copy A (read by half 0) at +0,  copy B (read by half 1) at +132
// 132-float shift => the two broadcast lines land in different banks.
#define PAR_STRIDE 264

__global__ void __launch_bounds__(THREADS, 1) fused_kernel(
    const float* __restrict__ latent,  // (64,128)
    const float* __restrict__ W_hh,    // (384,128)
    const float* __restrict__ b_ih,    // (384,)
    const float* __restrict__ b_hh,    // (384,)
    const float* __restrict__ fc_W,    // (512,128)
    const float* __restrict__ fc_b,    // (512,)
    float* __restrict__ out)           // (64,2048,512)
{
    __shared__ __align__(16) float pool[32 * H];

    const int tid = threadIdx.x;

    if (blockIdx.x < NREC) {
        // === Recurrence: one batch/CTA; a lane PAIR owns hidden index li.   ===
        // === TWO-PHASE dot: r+z first (their reduce/sigmoid chains resolve  ===
        // === under the n-dot), n second. Ping-pong h, ONE barrier per step. ===
        const int b    = blockIdx.x;
        const int lane = tid & 31;
        const int warp = tid >> 5;            // 0..7
        const int half = lane & 1;            // low/high 64 elems of each dot
        const int li   = warp * 16 + (lane >> 1);   // 0..127

        // Three half-rows of W_hh in registers: 96 u64 = 192 regs
        unsigned long long wr[32], wz[32], wn[32];
        {
            const unsigned long long* W64 = (const unsigned long long*)W_hh;
            const size_t o  = (size_t)half * 32;
            const size_t rr = (size_t)li * 64;
            const size_t rz = (size_t)(H + li) * 64;
            const size_t rn = (size_t)(2 * H + li) * 64;
            #pragma unroll
            for (int k = 0; k < 32; k++) wr[k] = W64[rr + o + k];
            #pragma unroll
            for (int k = 0; k < 32; k++) wz[k] = W64[rz + o + k];
            #pragma unroll
            for (int k = 0; k < 32; k++) wn[k] = W64[rn + o + k];
        }

        const float bs_r   = b_ih[li] + b_hh[li];
        const float bs_z   = b_ih[H + li] + b_hh[H + li];
        const float bs_n   = b_hh[2 * H + li];
        const float b_in_i = b_ih[2 * H + li];

        // h[li] lives in a register across steps (owned by this lane pair)
        float hold = latent[(size_t)b * H + li];
        pool[half * 132 + li] = hold;          // init parity-0 buffers
        __syncthreads();

        const int widx = half * 132 + li;      // write index within a parity region
        const int roff = half ? 196 : 0;       // read offset within a parity region

        const float* rb0 = pool + roff;              // parity 0 read base
        const float* rb1 = pool + PAR_STRIDE + roff; // parity 1 read base
        float*       wb0 = pool;                     // parity 0 write base
        float*       wb1 = pool + PAR_STRIDE;

        float* hs_base = g_hs + (size_t)b * SEQ * H + li;

        // one GRU step: read h from rbase, write new h to wbase
        auto step = [&](const float* rbase, float* wbase, int t) {
            const ulonglong2* h2 = (const ulonglong2*)rbase;

            // ---- phase 1: r and z dots (hv reused 2x, two acc chains) ----
            unsigned long long ar = 0ull, az = 0ull;
            #pragma unroll
            for (int k = 0; k < 16; k++) {
                ulonglong2 hv = h2[k];
                ar = ffma2(wr[2 * k],     hv.x, ar);
                az = ffma2(wz[2 * k],     hv.x, az);
                ar = ffma2(wr[2 * k + 1], hv.y, ar);
                az = ffma2(wz[2 * k + 1], hv.y, az);
            }
            float sr  = hsum2(ar);
            float sz  = hsum2(az);
            float sro = __shfl_xor_sync(0xffffffffu, sr, 1);
            float szo = __shfl_xor_sync(0xffffffffu, sz, 1);
            // r/z chains resolve while phase 2 issues below
            float r = fast_sigmoid(sr + sro + bs_r);
            float z = fast_sigmoid(sz + szo + bs_z);

            // ---- phase 2: n dot (reloads hv; LDS proven free) ----
            unsigned long long n0 = 0ull, n1 = 0ull;
            #pragma unroll
            for (int k = 0; k < 16; k++) {
                ulonglong2 hv = h2[k];
                n0 = ffma2(wn[2 * k],     hv.x, n0);
                n1 = ffma2(wn[2 * k + 1], hv.y, n1);
            }
            float sn  = hsum2(add2(n0, n1));
            float sno = __shfl_xor_sync(0xffffffffu, sn, 1);

            // exposed tail: hsum + shfl + add + tanh + 2 fma
            float n  = tanh_fast(fmaf(r, sn + sno + bs_n, b_in_i));
            float hn = fmaf(z, hold - n, n);     // (1-z)*n + z*h
            hold = hn;

            wbase[widx] = hn;                    // ping-pong write (no WAR race)
            if (half == 0) hs_base[(size_t)t * H] = hn;
            __syncthreads();                     // single barrier per step
        };

        for (int to = 0; to < SEQ; to += 32) {
            #pragma unroll 1
            for (int ti = 0; ti < 32; ti += 2) {
                step(rb0, wb1, to + ti);         // even step: parity 0 -> 1
                step(rb1, wb0, to + ti + 1);     // odd  step: parity 1 -> 0
            }
            if (tid == 0) {
                __threadfence();
                atomicExch(&g_wm[b], to + 32);
            }
        }
    } else {
        // ================= FC role: consume hs tiles as produced =================
        const int fcid = blockIdx.x - NREC;   // 0..83
        const int cb   = fcid / 21;           // fixed 128-col block
        const int sub  = fcid % 21;
        const int col  = cb * H + (tid & 127);
        const int grp  = tid >> 7;            // 2 row-groups over the 32-row tile

        unsigned long long w[64];
        {
            const unsigned long long* Wr =
                (const unsigned long long*)(fc_W + (size_t)col * H);
            #pragma unroll
            for (int k = 0; k < 64; k++) w[k] = Wr[k];
        }
        const float bias = fc_b[col];

        for (int ent = sub; ent < 64 * B; ent += 21) {
            const int tblk = ent >> 6;
            const int bb   = ent & 63;

            if (tid == 0) {
                const int need = (tblk + 1) * 32;
                while (atomicAdd(&g_wm[bb], 0) < need) __nanosleep(256);
            }
            __syncthreads();

            // Stage 32x128 fp32 hs tile (16 KB)
            const float4* src =
                (const float4*)(g_hs + ((size_t)bb * SEQ + (size_t)tblk * 32) * H);
            float4* dst = (float4*)pool;
            #pragma unroll
            for (int it = 0; it < 4; it++) {
                int idx = tid + it * THREADS;
                dst[idx] = src[idx];
            }
            __syncthreads();

            for (int r = grp; r < 32; r += 2) {
                const ulonglong2* hrow = (const ulonglong2*)(pool + r * H);
                unsigned long long a0 = 0ull, a1 = 0ull;
                #pragma unroll
                for (int k = 0; k < 32; k++) {
                    ulonglong2 hv = hrow[k];
                    a0 = ffma2(w[2 * k    ], hv.x, a0);
                    a1 = ffma2(w[2 * k + 1], hv.y, a1);
                }
                out[((size_t)bb * SEQ + (size_t)tblk * 32 + r) * OUTF + col] =
                    hsum2(add2(a0, a1)) + bias;
            }
            __syncthreads();
        }
    }
}

extern "C" void kernel_launch(void* const* d_in, const int* in_sizes, int n_in,
                              void* d_out, int out_size) {
    const float* latent = (const float*)d_in[0];
    const float* W_hh   = (const float*)d_in[1];
    const float* b_ih   = (const float*)d_in[2];
    const float* b_hh   = (const float*)d_in[3];
    const float* fc_W   = (const float*)d_in[4];
    const float* fc_b   = (const float*)d_in[5];
    float* out = (float*)d_out;

    init_wm_kernel<<<1, 64>>>();
    fused_kernel<<<NREC + NFC, THREADS>>>(latent, W_hh, b_ih, b_hh, fc_W, fc_b, out);
}